// round 14
// baseline (speedup 1.0000x reference)
#include <cuda_runtime.h>
#include <cuda_fp16.h>
#include <cstdint>

// RNNModel: g = [E|R]@[We|Wr]^T + (be+br+bh)  (proj, relu on t==0 rows)
//           h_t = relu(g_t + h_{t-1}@Wh^T)    (7 in-place GEMM launches)
//           need = h_7^T
// R13 (best: 1030us, proj 450us @ tensor 76%) + R14: K-stage 64 -> 128 to halve
//     per-tile fixed overhead (barrier/stageLoad/ldF) fraction; 2-stage smem
//     (209KB); SROWB=272 (conflict-free ldmatrix at 17*i mod 32 granules).
// NOTE: tcgen05 unusable in this harness build (ptxas targets compute_103 base).

#define STAGES    2
#define SROWB     272                   // bytes per smem row (128 halfs + 16B pad)
#define A_STAGE_B (256 * SROWB)         // 69632
#define B_STAGE_B (128 * SROWB)         // 34816
#define A_REGION  (STAGES * A_STAGE_B)  // 139264
#define SMEM_SZ   (A_REGION + STAGES * B_STAGE_B + 512)   // 209920

// fp16 scratch (device-global: allocation-free)
__device__ __half g_A16[(size_t)65536 * 1536];   // packed [E|R]
__device__ __half g_W16[1024 * 1536];            // packed [We|Wr]
__device__ __half g_Wh16[1024 * 1024];
__device__ __half g_H16[(size_t)65536 * 1024];   // h_t fp16, same row indexing as out

__device__ __forceinline__ void mma_f16(float c[4], const unsigned a[4], const unsigned b[2]) {
    asm volatile(
        "mma.sync.aligned.m16n8k16.row.col.f32.f16.f16.f32 "
        "{%0,%1,%2,%3}, {%4,%5,%6,%7}, {%8,%9}, {%0,%1,%2,%3};\n"
        : "+f"(c[0]), "+f"(c[1]), "+f"(c[2]), "+f"(c[3])
        : "r"(a[0]), "r"(a[1]), "r"(a[2]), "r"(a[3]),
          "r"(b[0]), "r"(b[1]));
}
__device__ __forceinline__ void ldsm_x4(unsigned& r0, unsigned& r1, unsigned& r2, unsigned& r3,
                                        unsigned addr) {
    asm volatile("ldmatrix.sync.aligned.m8n8.x4.shared.b16 {%0,%1,%2,%3}, [%4];\n"
                 : "=r"(r0), "=r"(r1), "=r"(r2), "=r"(r3)
                 : "r"(addr));
}
__device__ __forceinline__ void cp16(unsigned dst, const __half* src) {
    asm volatile("cp.async.cg.shared.global [%0], [%1], 16;" :: "r"(dst), "l"(src));
}
__device__ __forceinline__ void cp_commit() {
    asm volatile("cp.async.commit_group;" ::: "memory");
}
__device__ __forceinline__ void cp_wait1() {
    asm volatile("cp.async.wait_group 1;" ::: "memory");
}

// MODE 0: C[65536,1024] = A16 @ W16^T + bias; relu + H16 write on rows%8==0.
// MODE 1: C(+t*1024 by host) = relu(C + H16(t-1) @ Wh16^T); writes H16(t).
template<int MODE>
__global__ __launch_bounds__(256, 1)
void gemm16(int t, const float* __restrict__ be, const float* __restrict__ br,
            const float* __restrict__ bhp, float* C)
{
    constexpr int KTOT = MODE ? 1024 : 1536;
    constexpr int NKT  = KTOT / 128;
    constexpr int LDA  = MODE ? 8192 : 1536;
    constexpr int LDB  = MODE ? 1024 : 1536;
    constexpr int LDC  = MODE ? 8192 : 1024;

    extern __shared__ __align__(16) char sm[];
    float* sBias = (float*)(sm + A_REGION + STAGES * B_STAGE_B);
    const unsigned smBase = (unsigned)__cvta_generic_to_shared(sm);

    const int tid = threadIdx.x;
    const int bN  = blockIdx.x;
    const int bM  = blockIdx.y;

    const __half* A = MODE ? g_H16 + (size_t)(t - 1) * 1024 : g_A16;
    const __half* B = MODE ? g_Wh16 : g_W16;
    __half* Hout = MODE ? g_H16 + (size_t)t * 1024 : g_H16;
    const int ldH = MODE ? 8192 : 1024;

    if (MODE == 0) {
        if (tid < 128) {
            int c = bN * 128 + tid;
            sBias[tid] = be[c] + br[c] + bhp[c];
        }
    }

    const int lane = tid & 31;
    const int warp = tid >> 5;
    const int wm = warp & 3;      // 4 M-warps of 64 rows
    const int wn = warp >> 2;     // 2 N-warps of 64 cols
    const int g8  = lane >> 2;    // 0..7
    const int qid = lane & 3;

    // --- pointer-stepped cp.async state (K-stage 128: 16 chunks/row) ---
    const int srow = tid >> 4;    // 0..15
    const int sch  = tid & 15;    // 16B chunk in 256B row
    const __half* aG = A + (size_t)(bM * 256 + srow) * LDA + sch * 8;
    const __half* bG = B + (size_t)(bN * 128 + srow) * LDB + sch * 8;
    const unsigned dA0 = smBase + srow * SROWB + sch * 16;
    const unsigned dB0 = smBase + A_REGION + srow * SROWB + sch * 16;
    int stIdx = 0;

    auto stageLoad = [&]() {
        const unsigned sA = dA0 + stIdx * A_STAGE_B;
        const unsigned sB = dB0 + stIdx * B_STAGE_B;
        #pragma unroll
        for (int i = 0; i < 16; ++i)   // A: 256 rows, 16 per pass
            cp16(sA + i * (16 * SROWB), aG + (size_t)i * 16 * LDA);
        #pragma unroll
        for (int i = 0; i < 8; ++i)    // B: 128 rows
            cp16(sB + i * (16 * SROWB), bG + (size_t)i * 16 * LDB);
        cp_commit();
        aG += 128; bG += 128;
        stIdx ^= 1;
    };

    // ldmatrix base addresses (stage 0)
    const int rA = wm * 64 + (lane & 7) + ((lane >> 3) & 1) * 8;
    const int kselA = (lane >> 4) & 1;
    const unsigned aAddr0 = smBase + (unsigned)(rA * SROWB + kselA * 16);
    const int rB = wn * 64 + (lane & 7) + ((lane >> 4) & 1) * 8;
    const int kselB = (lane >> 3) & 1;
    const unsigned bAddr0 = smBase + (unsigned)(A_REGION + rB * SROWB + kselB * 16);

    // fragment double buffer
    unsigned af0[4][4], af1[4][4], bf0[8][2], bf1[8][2];

    auto ldF = [&](unsigned (&af)[4][4], unsigned (&bf)[8][2], unsigned offA, unsigned offB) {
        #pragma unroll
        for (int mt = 0; mt < 4; ++mt)
            ldsm_x4(af[mt][0], af[mt][1], af[mt][2], af[mt][3],
                    aAddr0 + offA + mt * (16 * SROWB));
        #pragma unroll
        for (int p = 0; p < 4; ++p)
            ldsm_x4(bf[2 * p][0], bf[2 * p][1], bf[2 * p + 1][0], bf[2 * p + 1][1],
                    bAddr0 + offB + p * (16 * SROWB));
    };

    float acc[4][8][4];
    #pragma unroll
    for (int mt = 0; mt < 4; ++mt)
        #pragma unroll
        for (int nt = 0; nt < 8; ++nt)
            #pragma unroll
            for (int j = 0; j < 4; ++j) acc[mt][nt][j] = 0.f;

    auto mmaF = [&](unsigned (&af)[4][4], unsigned (&bf)[8][2]) {
        #pragma unroll
        for (int mt = 0; mt < 4; ++mt)
            #pragma unroll
            for (int nt = 0; nt < 8; ++nt)
                mma_f16(acc[mt][nt], af[mt], bf[nt]);
    };

    // prologue: both slots issued; stage 0 guaranteed (wait1); prime ks0
    stageLoad(); stageLoad();
    cp_wait1();
    __syncthreads();
    ldF(af0, bf0, 0u, 0u);

    unsigned curA = 0, curB = 0;
    for (int kt = 0; kt < NKT; ++kt) {
        // 8 ks steps, fragment double-buffered; even ks in f0, odd in f1
        #pragma unroll
        for (int ks = 0; ks < 8; ks += 2) {
            ldF(af1, bf1, curA + ks * 32u + 32u, curB + ks * 32u + 32u);   // ks+1
            mmaF(af0, bf0);                                               // ks
            if (ks + 2 < 8)
                ldF(af0, bf0, curA + ks * 32u + 64u, curB + ks * 32u + 64u); // ks+2
            mmaF(af1, bf1);                                               // ks+1 (ks7 queued pre-barrier)
        }

        cp_wait1();          // stage kt+1 landed; barrier hides under HMMA drain
        __syncthreads();

        if (kt + 2 < NKT) stageLoad();   // into the slot just freed (stage kt's)
        else cp_commit();                // keep wait_group accounting in order
        curA ^= A_STAGE_B;
        curB ^= B_STAGE_B;
        if (kt + 1 < NKT) ldF(af0, bf0, curA, curB);  // next tile ks0
    }

    // epilogue
    #pragma unroll
    for (int mt = 0; mt < 4; ++mt) {
        int r0 = bM * 256 + wm * 64 + mt * 16 + g8;
        #pragma unroll
        for (int nt = 0; nt < 8; ++nt) {
            int col  = bN * 128 + wn * 64 + nt * 8 + qid * 2;
            int colL = wn * 64 + nt * 8 + qid * 2;
            if (MODE == 0) {
                float b0 = sBias[colL];
                float b1 = sBias[colL + 1];
                float x0 = acc[mt][nt][0] + b0;
                float x1 = acc[mt][nt][1] + b1;
                float x2 = acc[mt][nt][2] + b0;
                float x3 = acc[mt][nt][3] + b1;
                if (g8 == 0) {   // rows%8==0 are t==0: relu + fp16 h0
                    x0 = fmaxf(x0, 0.f); x1 = fmaxf(x1, 0.f);
                    x2 = fmaxf(x2, 0.f); x3 = fmaxf(x3, 0.f);
                    *(__half2*)(Hout + (size_t)r0 * ldH + col)       = __floats2half2_rn(x0, x1);
                    *(__half2*)(Hout + (size_t)(r0 + 8) * ldH + col) = __floats2half2_rn(x2, x3);
                }
                *(float2*)(C + (size_t)r0 * LDC + col)       = make_float2(x0, x1);
                *(float2*)(C + (size_t)(r0 + 8) * LDC + col) = make_float2(x2, x3);
            } else {
                float* p0 = C + (size_t)r0 * LDC + col;
                float* p1 = C + (size_t)(r0 + 8) * LDC + col;
                float2 g0 = *(float2*)p0;
                float2 g1 = *(float2*)p1;
                float x0 = fmaxf(acc[mt][nt][0] + g0.x, 0.f);
                float x1 = fmaxf(acc[mt][nt][1] + g0.y, 0.f);
                float x2 = fmaxf(acc[mt][nt][2] + g1.x, 0.f);
                float x3 = fmaxf(acc[mt][nt][3] + g1.y, 0.f);
                *(float2*)p0 = make_float2(x0, x1);
                *(float2*)p1 = make_float2(x2, x3);
                *(__half2*)(Hout + (size_t)r0 * ldH + col)       = __floats2half2_rn(x0, x1);
                *(__half2*)(Hout + (size_t)(r0 + 8) * ldH + col) = __floats2half2_rn(x2, x3);
            }
        }
    }
}

// pack two fp32 sources (widths 512 and 1024) into one fp16 row of 1536.
// One row per block, 192 threads, no integer division.
template<int DST>  // 0 -> g_A16, 1 -> g_W16
__global__ void pack16(const float* __restrict__ s0, const float* __restrict__ s1)
{
    __half* dst = DST ? g_W16 : g_A16;
    const int row = blockIdx.x;
    const int c8  = threadIdx.x * 8;
    const float* p = (c8 < 512) ? (s0 + (size_t)row * 512 + c8)
                                : (s1 + (size_t)row * 1024 + (c8 - 512));
    float4 v0 = ((const float4*)p)[0];
    float4 v1 = ((const float4*)p)[1];
    __half2 h0 = __floats2half2_rn(v0.x, v0.y);
    __half2 h1 = __floats2half2_rn(v0.z, v0.w);
    __half2 h2 = __floats2half2_rn(v1.x, v1.y);
    __half2 h3 = __floats2half2_rn(v1.z, v1.w);
    uint4 o = make_uint4(*(unsigned*)&h0, *(unsigned*)&h1, *(unsigned*)&h2, *(unsigned*)&h3);
    *(uint4*)(dst + (size_t)row * 1536 + c8) = o;
}

__global__ void cvt16(const float* __restrict__ src, int n)   // -> g_Wh16
{
    size_t i = ((size_t)blockIdx.x * 256 + threadIdx.x) * 8;
    if (i >= (size_t)n) return;
    float4 v0 = ((const float4*)(src + i))[0];
    float4 v1 = ((const float4*)(src + i))[1];
    __half2 h0 = __floats2half2_rn(v0.x, v0.y);
    __half2 h1 = __floats2half2_rn(v0.z, v0.w);
    __half2 h2 = __floats2half2_rn(v1.x, v1.y);
    __half2 h3 = __floats2half2_rn(v1.z, v1.w);
    *(uint4*)(g_Wh16 + i) = make_uint4(*(unsigned*)&h0, *(unsigned*)&h1,
                                       *(unsigned*)&h2, *(unsigned*)&h3);
}

// need[h, b] = out[b, 7, h]
__global__ void transpose_k(const float* __restrict__ out, float* __restrict__ need)
{
    __shared__ float tile[32][33];
    int h0 = blockIdx.x * 32;
    int b0 = blockIdx.y * 32;
    int x = threadIdx.x;
    int y = threadIdx.y;
    #pragma unroll
    for (int j = 0; j < 32; j += 8)
        tile[y + j][x] = out[(size_t)(b0 + y + j) * 8192 + 7168 + h0 + x];
    __syncthreads();
    #pragma unroll
    for (int j = 0; j < 32; j += 8)
        need[(size_t)(h0 + y + j) * 8192 + b0 + x] = tile[x][y + j];
}

extern "C" void kernel_launch(void* const* d_in, const int* in_sizes, int n_in,
                              void* d_out, int out_size)
{
    const float* entity   = (const float*)d_in[0];
    const float* relation = (const float*)d_in[1];
    const float* We       = (const float*)d_in[2];
    const float* be       = (const float*)d_in[3];
    const float* Wr       = (const float*)d_in[4];
    const float* br       = (const float*)d_in[5];
    const float* Wh       = (const float*)d_in[6];
    const float* bh       = (const float*)d_in[7];

    float* out  = (float*)d_out;               // [65536, 1024]
    float* need = out + (size_t)65536 * 1024;  // [1024, 8192]

    cudaFuncSetAttribute(gemm16<0>, cudaFuncAttributeMaxDynamicSharedMemorySize, SMEM_SZ);
    cudaFuncSetAttribute(gemm16<1>, cudaFuncAttributeMaxDynamicSharedMemorySize, SMEM_SZ);

    // prepass: fp16 conversions
    pack16<0><<<65536, 192>>>(entity, relation);
    pack16<1><<<1024, 192>>>(We, Wr);
    cvt16<<<(1024 * 1024 / 8 + 255) / 256, 256>>>(Wh, 1024 * 1024);

    // projection: M tiles = 256, N tiles = 8 (bN fastest -> A-block L2 reuse)
    gemm16<0><<<dim3(8, 256), 256, SMEM_SZ>>>(0, be, br, bh, out);

    // recurrence: M tiles = 32, N tiles = 8
    for (int t = 1; t < 8; ++t)
        gemm16<1><<<dim3(8, 32), 256, SMEM_SZ>>>(t, nullptr, nullptr, nullptr,
                                                 out + (size_t)t * 1024);

    transpose_k<<<dim3(32, 256), dim3(32, 8)>>>(out, need);
}

// round 15
// speedup vs baseline: 1.1371x; 1.1371x over previous
#include <cuda_runtime.h>
#include <cuda_fp16.h>
#include <cstdint>

// RNNModel: g = [E|R]@[We|Wr]^T + (be+br+bh)  (proj, relu on t==0 rows)
//           h_t = relu(g_t + h_{t-1}@Wh^T)    (7 in-place GEMM launches)
//           need = h_7^T
// R13 config (best: 1030us, proj 450us @ tensor 76%) + R15: ks-phase stagger —
//     wn=1 warps traverse ks rotated by 2 so the two warps per SMSP interleave
//     LDSM and HMMA bursts instead of running in barrier-lockstep.
// NOTE: tcgen05 unusable in this harness build (ptxas targets compute_103 base).

#define STAGES    3
#define SROWB     144                   // bytes per smem row (64 halfs + pad)
#define A_STAGE_B (256 * SROWB)         // 36864
#define B_STAGE_B (128 * SROWB)         // 18432
#define A_REGION  (STAGES * A_STAGE_B)  // 110592
#define SMEM_SZ   (A_REGION + STAGES * B_STAGE_B + 512)   // 166400

// fp16 scratch (device-global: allocation-free)
__device__ __half g_A16[(size_t)65536 * 1536];   // packed [E|R]
__device__ __half g_W16[1024 * 1536];            // packed [We|Wr]
__device__ __half g_Wh16[1024 * 1024];
__device__ __half g_H16[(size_t)65536 * 1024];   // h_t fp16, same row indexing as out

__device__ __forceinline__ void mma_f16(float c[4], const unsigned a[4], const unsigned b[2]) {
    asm volatile(
        "mma.sync.aligned.m16n8k16.row.col.f32.f16.f16.f32 "
        "{%0,%1,%2,%3}, {%4,%5,%6,%7}, {%8,%9}, {%0,%1,%2,%3};\n"
        : "+f"(c[0]), "+f"(c[1]), "+f"(c[2]), "+f"(c[3])
        : "r"(a[0]), "r"(a[1]), "r"(a[2]), "r"(a[3]),
          "r"(b[0]), "r"(b[1]));
}
__device__ __forceinline__ void ldsm_x4(unsigned& r0, unsigned& r1, unsigned& r2, unsigned& r3,
                                        unsigned addr) {
    asm volatile("ldmatrix.sync.aligned.m8n8.x4.shared.b16 {%0,%1,%2,%3}, [%4];\n"
                 : "=r"(r0), "=r"(r1), "=r"(r2), "=r"(r3)
                 : "r"(addr));
}
__device__ __forceinline__ void cp16(unsigned dst, const __half* src) {
    asm volatile("cp.async.cg.shared.global [%0], [%1], 16;" :: "r"(dst), "l"(src));
}
__device__ __forceinline__ void cp_commit() {
    asm volatile("cp.async.commit_group;" ::: "memory");
}
__device__ __forceinline__ void cp_wait1() {
    asm volatile("cp.async.wait_group 1;" ::: "memory");
}

// MODE 0: C[65536,1024] = A16 @ W16^T + bias; relu + H16 write on rows%8==0.
// MODE 1: C(+t*1024 by host) = relu(C + H16(t-1) @ Wh16^T); writes H16(t).
template<int MODE>
__global__ __launch_bounds__(256, 1)
void gemm16(int t, const float* __restrict__ be, const float* __restrict__ br,
            const float* __restrict__ bhp, float* C)
{
    constexpr int KTOT = MODE ? 1024 : 1536;
    constexpr int NKT  = KTOT / 64;
    constexpr int LDA  = MODE ? 8192 : 1536;
    constexpr int LDB  = MODE ? 1024 : 1536;
    constexpr int LDC  = MODE ? 8192 : 1024;

    extern __shared__ __align__(16) char sm[];
    float* sBias = (float*)(sm + A_REGION + STAGES * B_STAGE_B);
    const unsigned smBase = (unsigned)__cvta_generic_to_shared(sm);

    const int tid = threadIdx.x;
    const int bN  = blockIdx.x;
    const int bM  = blockIdx.y;

    const __half* A = MODE ? g_H16 + (size_t)(t - 1) * 1024 : g_A16;
    const __half* B = MODE ? g_Wh16 : g_W16;
    __half* Hout = MODE ? g_H16 + (size_t)t * 1024 : g_H16;
    const int ldH = MODE ? 8192 : 1024;

    if (MODE == 0) {
        if (tid < 128) {
            int c = bN * 128 + tid;
            sBias[tid] = be[c] + br[c] + bhp[c];
        }
    }

    const int lane = tid & 31;
    const int warp = tid >> 5;
    const int wm = warp & 3;      // 4 M-warps of 64 rows
    const int wn = warp >> 2;     // 2 N-warps of 64 cols
    const int g8  = lane >> 2;    // 0..7
    const int qid = lane & 3;

    // ks-phase stagger: SMSP = warp%4, so warps w and w+4 share one SMSP and
    // have different wn. Rotate wn=1 warps' ks order by 2 (byte offset 64).
    const unsigned kph = wn ? 64u : 0u;
    auto KO = [&](int s) -> unsigned { return (kph + (unsigned)s * 32u) & 96u; };

    // --- pointer-stepped cp.async state (all offsets compile-time) ---
    const int srow = tid >> 3;    // 0..31
    const int sch  = tid & 7;     // 16B chunk in row
    const __half* aG = A + (size_t)(bM * 256 + srow) * LDA + sch * 8;
    const __half* bG = B + (size_t)(bN * 128 + srow) * LDB + sch * 8;
    const unsigned dA0 = smBase + srow * SROWB + sch * 16;
    const unsigned dB0 = smBase + A_REGION + srow * SROWB + sch * 16;
    int stIdx = 0;

    auto stageLoad = [&]() {
        const unsigned sA = dA0 + stIdx * A_STAGE_B;
        const unsigned sB = dB0 + stIdx * B_STAGE_B;
        #pragma unroll
        for (int i = 0; i < 8; ++i)
            cp16(sA + i * (32 * SROWB), aG + (size_t)i * 32 * LDA);
        #pragma unroll
        for (int i = 0; i < 4; ++i)
            cp16(sB + i * (32 * SROWB), bG + (size_t)i * 32 * LDB);
        cp_commit();
        aG += 64; bG += 64;
        stIdx = (stIdx == STAGES - 1) ? 0 : stIdx + 1;
    };

    // ldmatrix base addresses (stage 0)
    const int rA = wm * 64 + (lane & 7) + ((lane >> 3) & 1) * 8;
    const int kselA = (lane >> 4) & 1;
    const unsigned aAddr0 = smBase + (unsigned)(rA * SROWB + kselA * 16);
    const int rB = wn * 64 + (lane & 7) + ((lane >> 4) & 1) * 8;
    const int kselB = (lane >> 3) & 1;
    const unsigned bAddr0 = smBase + (unsigned)(A_REGION + rB * SROWB + kselB * 16);

    // fragment double buffer
    unsigned af0[4][4], af1[4][4], bf0[8][2], bf1[8][2];

    auto ldF = [&](unsigned (&af)[4][4], unsigned (&bf)[8][2], unsigned offA, unsigned offB) {
        #pragma unroll
        for (int mt = 0; mt < 4; ++mt)
            ldsm_x4(af[mt][0], af[mt][1], af[mt][2], af[mt][3],
                    aAddr0 + offA + mt * (16 * SROWB));
        #pragma unroll
        for (int p = 0; p < 4; ++p)
            ldsm_x4(bf[2 * p][0], bf[2 * p][1], bf[2 * p + 1][0], bf[2 * p + 1][1],
                    bAddr0 + offB + p * (16 * SROWB));
    };

    float acc[4][8][4];
    #pragma unroll
    for (int mt = 0; mt < 4; ++mt)
        #pragma unroll
        for (int nt = 0; nt < 8; ++nt)
            #pragma unroll
            for (int j = 0; j < 4; ++j) acc[mt][nt][j] = 0.f;

    auto mmaF = [&](unsigned (&af)[4][4], unsigned (&bf)[8][2]) {
        #pragma unroll
        for (int mt = 0; mt < 4; ++mt)
            #pragma unroll
            for (int nt = 0; nt < 8; ++nt)
                mma_f16(acc[mt][nt], af[mt], bf[nt]);
    };

    // prologue: stages 0,1 issued; stage 0 guaranteed (wait1)
    stageLoad(); stageLoad();
    cp_wait1();
    __syncthreads();
    ldF(af0, bf0, KO(0), KO(0));

    unsigned curA = 0, curB = 0;
    for (int kt = 0; kt < NKT; ++kt) {
        ldF(af1, bf1, curA + KO(1), curB + KO(1));    // step 1
        mmaF(af0, bf0);                               // step 0
        if (kt + 2 < NKT) stageLoad();                // issued under MMA shadow
        else cp_commit();                             // keep group accounting in order
        ldF(af0, bf0, curA + KO(2), curB + KO(2));    // step 2
        mmaF(af1, bf1);                               // step 1
        ldF(af1, bf1, curA + KO(3), curB + KO(3));    // step 3
        mmaF(af0, bf0);                               // step 2
        mmaF(af1, bf1);                               // step 3 — full backlog queued

        cp_wait1();          // stage kt+1 done (2-iter-old); kt+2 may still fly
        __syncthreads();     // hides under HMMA drain

        curA = (curA == (STAGES - 1) * A_STAGE_B) ? 0u : curA + A_STAGE_B;
        curB = (curB == (STAGES - 1) * B_STAGE_B) ? 0u : curB + B_STAGE_B;
        if (kt + 1 < NKT) ldF(af0, bf0, curA + KO(0), curB + KO(0));  // next tile step 0
    }

    // epilogue
    #pragma unroll
    for (int mt = 0; mt < 4; ++mt) {
        int r0 = bM * 256 + wm * 64 + mt * 16 + g8;
        #pragma unroll
        for (int nt = 0; nt < 8; ++nt) {
            int col  = bN * 128 + wn * 64 + nt * 8 + qid * 2;
            int colL = wn * 64 + nt * 8 + qid * 2;
            if (MODE == 0) {
                float b0 = sBias[colL];
                float b1 = sBias[colL + 1];
                float x0 = acc[mt][nt][0] + b0;
                float x1 = acc[mt][nt][1] + b1;
                float x2 = acc[mt][nt][2] + b0;
                float x3 = acc[mt][nt][3] + b1;
                if (g8 == 0) {   // rows%8==0 are t==0: relu + fp16 h0
                    x0 = fmaxf(x0, 0.f); x1 = fmaxf(x1, 0.f);
                    x2 = fmaxf(x2, 0.f); x3 = fmaxf(x3, 0.f);
                    *(__half2*)(Hout + (size_t)r0 * ldH + col)       = __floats2half2_rn(x0, x1);
                    *(__half2*)(Hout + (size_t)(r0 + 8) * ldH + col) = __floats2half2_rn(x2, x3);
                }
                *(float2*)(C + (size_t)r0 * LDC + col)       = make_float2(x0, x1);
                *(float2*)(C + (size_t)(r0 + 8) * LDC + col) = make_float2(x2, x3);
            } else {
                float* p0 = C + (size_t)r0 * LDC + col;
                float* p1 = C + (size_t)(r0 + 8) * LDC + col;
                float2 g0 = *(float2*)p0;
                float2 g1 = *(float2*)p1;
                float x0 = fmaxf(acc[mt][nt][0] + g0.x, 0.f);
                float x1 = fmaxf(acc[mt][nt][1] + g0.y, 0.f);
                float x2 = fmaxf(acc[mt][nt][2] + g1.x, 0.f);
                float x3 = fmaxf(acc[mt][nt][3] + g1.y, 0.f);
                *(float2*)p0 = make_float2(x0, x1);
                *(float2*)p1 = make_float2(x2, x3);
                *(__half2*)(Hout + (size_t)r0 * ldH + col)       = __floats2half2_rn(x0, x1);
                *(__half2*)(Hout + (size_t)(r0 + 8) * ldH + col) = __floats2half2_rn(x2, x3);
            }
        }
    }
}

// pack two fp32 sources (widths 512 and 1024) into one fp16 row of 1536.
// One row per block, 192 threads, no integer division.
template<int DST>  // 0 -> g_A16, 1 -> g_W16
__global__ void pack16(const float* __restrict__ s0, const float* __restrict__ s1)
{
    __half* dst = DST ? g_W16 : g_A16;
    const int row = blockIdx.x;
    const int c8  = threadIdx.x * 8;
    const float* p = (c8 < 512) ? (s0 + (size_t)row * 512 + c8)
                                : (s1 + (size_t)row * 1024 + (c8 - 512));
    float4 v0 = ((const float4*)p)[0];
    float4 v1 = ((const float4*)p)[1];
    __half2 h0 = __floats2half2_rn(v0.x, v0.y);
    __half2 h1 = __floats2half2_rn(v0.z, v0.w);
    __half2 h2 = __floats2half2_rn(v1.x, v1.y);
    __half2 h3 = __floats2half2_rn(v1.z, v1.w);
    uint4 o = make_uint4(*(unsigned*)&h0, *(unsigned*)&h1, *(unsigned*)&h2, *(unsigned*)&h3);
    *(uint4*)(dst + (size_t)row * 1536 + c8) = o;
}

__global__ void cvt16(const float* __restrict__ src, int n)   // -> g_Wh16
{
    size_t i = ((size_t)blockIdx.x * 256 + threadIdx.x) * 8;
    if (i >= (size_t)n) return;
    float4 v0 = ((const float4*)(src + i))[0];
    float4 v1 = ((const float4*)(src + i))[1];
    __half2 h0 = __floats2half2_rn(v0.x, v0.y);
    __half2 h1 = __floats2half2_rn(v0.z, v0.w);
    __half2 h2 = __floats2half2_rn(v1.x, v1.y);
    __half2 h3 = __floats2half2_rn(v1.z, v1.w);
    *(uint4*)(g_Wh16 + i) = make_uint4(*(unsigned*)&h0, *(unsigned*)&h1,
                                       *(unsigned*)&h2, *(unsigned*)&h3);
}

// need[h, b] = out[b, 7, h]
__global__ void transpose_k(const float* __restrict__ out, float* __restrict__ need)
{
    __shared__ float tile[32][33];
    int h0 = blockIdx.x * 32;
    int b0 = blockIdx.y * 32;
    int x = threadIdx.x;
    int y = threadIdx.y;
    #pragma unroll
    for (int j = 0; j < 32; j += 8)
        tile[y + j][x] = out[(size_t)(b0 + y + j) * 8192 + 7168 + h0 + x];
    __syncthreads();
    #pragma unroll
    for (int j = 0; j < 32; j += 8)
        need[(size_t)(h0 + y + j) * 8192 + b0 + x] = tile[x][y + j];
}

extern "C" void kernel_launch(void* const* d_in, const int* in_sizes, int n_in,
                              void* d_out, int out_size)
{
    const float* entity   = (const float*)d_in[0];
    const float* relation = (const float*)d_in[1];
    const float* We       = (const float*)d_in[2];
    const float* be       = (const float*)d_in[3];
    const float* Wr       = (const float*)d_in[4];
    const float* br       = (const float*)d_in[5];
    const float* Wh       = (const float*)d_in[6];
    const float* bh       = (const float*)d_in[7];

    float* out  = (float*)d_out;               // [65536, 1024]
    float* need = out + (size_t)65536 * 1024;  // [1024, 8192]

    cudaFuncSetAttribute(gemm16<0>, cudaFuncAttributeMaxDynamicSharedMemorySize, SMEM_SZ);
    cudaFuncSetAttribute(gemm16<1>, cudaFuncAttributeMaxDynamicSharedMemorySize, SMEM_SZ);

    // prepass: fp16 conversions
    pack16<0><<<65536, 192>>>(entity, relation);
    pack16<1><<<1024, 192>>>(We, Wr);
    cvt16<<<(1024 * 1024 / 8 + 255) / 256, 256>>>(Wh, 1024 * 1024);

    // projection: M tiles = 256, N tiles = 8 (bN fastest -> A-block L2 reuse)
    gemm16<0><<<dim3(8, 256), 256, SMEM_SZ>>>(0, be, br, bh, out);

    // recurrence: M tiles = 32, N tiles = 8
    for (int t = 1; t < 8; ++t)
        gemm16<1><<<dim3(8, 32), 256, SMEM_SZ>>>(t, nullptr, nullptr, nullptr,
                                                 out + (size_t)t * 1024);

    transpose_k<<<dim3(32, 256), dim3(32, 8)>>>(out, need);
}

// round 16
// speedup vs baseline: 1.1456x; 1.0075x over previous
#include <cuda_runtime.h>
#include <cuda_fp16.h>
#include <cstdint>

// RNNModel: g = [E|R]@[We|Wr]^T + (be+br+bh)  (proj, relu on t==0 rows)
//           h_t = relu(g_t + h_{t-1}@Wh^T)    (7 in-place GEMM launches)
//           need = h_7^T
// R15 config (best: 1026us) + R16: MODE 1 preloads g_t into the MMA
//     accumulators at kernel start (latency hidden under prologue) so the
//     epilogue is relu+store only — removes the cold RMW from the tail.
// NOTE: tcgen05 unusable in this harness build (ptxas targets compute_103 base).

#define STAGES    3
#define SROWB     144                   // bytes per smem row (64 halfs + pad)
#define A_STAGE_B (256 * SROWB)         // 36864
#define B_STAGE_B (128 * SROWB)         // 18432
#define A_REGION  (STAGES * A_STAGE_B)  // 110592
#define SMEM_SZ   (A_REGION + STAGES * B_STAGE_B + 512)   // 166400

// fp16 scratch (device-global: allocation-free)
__device__ __half g_A16[(size_t)65536 * 1536];   // packed [E|R]
__device__ __half g_W16[1024 * 1536];            // packed [We|Wr]
__device__ __half g_Wh16[1024 * 1024];
__device__ __half g_H16[(size_t)65536 * 1024];   // h_t fp16, same row indexing as out

__device__ __forceinline__ void mma_f16(float c[4], const unsigned a[4], const unsigned b[2]) {
    asm volatile(
        "mma.sync.aligned.m16n8k16.row.col.f32.f16.f16.f32 "
        "{%0,%1,%2,%3}, {%4,%5,%6,%7}, {%8,%9}, {%0,%1,%2,%3};\n"
        : "+f"(c[0]), "+f"(c[1]), "+f"(c[2]), "+f"(c[3])
        : "r"(a[0]), "r"(a[1]), "r"(a[2]), "r"(a[3]),
          "r"(b[0]), "r"(b[1]));
}
__device__ __forceinline__ void ldsm_x4(unsigned& r0, unsigned& r1, unsigned& r2, unsigned& r3,
                                        unsigned addr) {
    asm volatile("ldmatrix.sync.aligned.m8n8.x4.shared.b16 {%0,%1,%2,%3}, [%4];\n"
                 : "=r"(r0), "=r"(r1), "=r"(r2), "=r"(r3)
                 : "r"(addr));
}
__device__ __forceinline__ void cp16(unsigned dst, const __half* src) {
    asm volatile("cp.async.cg.shared.global [%0], [%1], 16;" :: "r"(dst), "l"(src));
}
__device__ __forceinline__ void cp_commit() {
    asm volatile("cp.async.commit_group;" ::: "memory");
}
__device__ __forceinline__ void cp_wait1() {
    asm volatile("cp.async.wait_group 1;" ::: "memory");
}

// MODE 0: C[65536,1024] = A16 @ W16^T + bias; relu + H16 write on rows%8==0.
// MODE 1: C(+t*1024 by host) = relu(g_t(preloaded acc) + H16(t-1) @ Wh16^T); writes H16(t).
template<int MODE>
__global__ __launch_bounds__(256, 1)
void gemm16(int t, const float* __restrict__ be, const float* __restrict__ br,
            const float* __restrict__ bhp, float* C)
{
    constexpr int KTOT = MODE ? 1024 : 1536;
    constexpr int NKT  = KTOT / 64;
    constexpr int LDA  = MODE ? 8192 : 1536;
    constexpr int LDB  = MODE ? 1024 : 1536;
    constexpr int LDC  = MODE ? 8192 : 1024;

    extern __shared__ __align__(16) char sm[];
    float* sBias = (float*)(sm + A_REGION + STAGES * B_STAGE_B);
    const unsigned smBase = (unsigned)__cvta_generic_to_shared(sm);

    const int tid = threadIdx.x;
    const int bN  = blockIdx.x;
    const int bM  = blockIdx.y;

    const __half* A = MODE ? g_H16 + (size_t)(t - 1) * 1024 : g_A16;
    const __half* B = MODE ? g_Wh16 : g_W16;
    __half* Hout = MODE ? g_H16 + (size_t)t * 1024 : g_H16;
    const int ldH = MODE ? 8192 : 1024;

    if (MODE == 0) {
        if (tid < 128) {
            int c = bN * 128 + tid;
            sBias[tid] = be[c] + br[c] + bhp[c];
        }
    }

    const int lane = tid & 31;
    const int warp = tid >> 5;
    const int wm = warp & 3;      // 4 M-warps of 64 rows
    const int wn = warp >> 2;     // 2 N-warps of 64 cols
    const int g8  = lane >> 2;    // 0..7
    const int qid = lane & 3;

    // ks-phase stagger (R15): wn=1 warps rotate the ks order by 2.
    const unsigned kph = wn ? 64u : 0u;
    auto KO = [&](int s) -> unsigned { return (kph + (unsigned)s * 32u) & 96u; };

    // --- pointer-stepped cp.async state (all offsets compile-time) ---
    const int srow = tid >> 3;    // 0..31
    const int sch  = tid & 7;     // 16B chunk in row
    const __half* aG = A + (size_t)(bM * 256 + srow) * LDA + sch * 8;
    const __half* bG = B + (size_t)(bN * 128 + srow) * LDB + sch * 8;
    const unsigned dA0 = smBase + srow * SROWB + sch * 16;
    const unsigned dB0 = smBase + A_REGION + srow * SROWB + sch * 16;
    int stIdx = 0;

    auto stageLoad = [&]() {
        const unsigned sA = dA0 + stIdx * A_STAGE_B;
        const unsigned sB = dB0 + stIdx * B_STAGE_B;
        #pragma unroll
        for (int i = 0; i < 8; ++i)
            cp16(sA + i * (32 * SROWB), aG + (size_t)i * 32 * LDA);
        #pragma unroll
        for (int i = 0; i < 4; ++i)
            cp16(sB + i * (32 * SROWB), bG + (size_t)i * 32 * LDB);
        cp_commit();
        aG += 64; bG += 64;
        stIdx = (stIdx == STAGES - 1) ? 0 : stIdx + 1;
    };

    // ldmatrix base addresses (stage 0)
    const int rA = wm * 64 + (lane & 7) + ((lane >> 3) & 1) * 8;
    const int kselA = (lane >> 4) & 1;
    const unsigned aAddr0 = smBase + (unsigned)(rA * SROWB + kselA * 16);
    const int rB = wn * 64 + (lane & 7) + ((lane >> 4) & 1) * 8;
    const int kselB = (lane >> 3) & 1;
    const unsigned bAddr0 = smBase + (unsigned)(A_REGION + rB * SROWB + kselB * 16);

    // fragment double buffer
    unsigned af0[4][4], af1[4][4], bf0[8][2], bf1[8][2];

    auto ldF = [&](unsigned (&af)[4][4], unsigned (&bf)[8][2], unsigned offA, unsigned offB) {
        #pragma unroll
        for (int mt = 0; mt < 4; ++mt)
            ldsm_x4(af[mt][0], af[mt][1], af[mt][2], af[mt][3],
                    aAddr0 + offA + mt * (16 * SROWB));
        #pragma unroll
        for (int p = 0; p < 4; ++p)
            ldsm_x4(bf[2 * p][0], bf[2 * p][1], bf[2 * p + 1][0], bf[2 * p + 1][1],
                    bAddr0 + offB + p * (16 * SROWB));
    };

    float acc[4][8][4];

    auto mmaF = [&](unsigned (&af)[4][4], unsigned (&bf)[8][2]) {
        #pragma unroll
        for (int mt = 0; mt < 4; ++mt)
            #pragma unroll
            for (int nt = 0; nt < 8; ++nt)
                mma_f16(acc[mt][nt], af[mt], bf[nt]);
    };

    // prologue: issue the async stage loads FIRST (cp.async never blocks)...
    stageLoad(); stageLoad();

    // ...then initialize accumulators. MODE 1: acc = g_t, loaded while the
    // prologue stages are in flight (latency hidden under cp_wait1 + tile 0).
    if (MODE == 1) {
        #pragma unroll
        for (int mt = 0; mt < 4; ++mt) {
            const size_t r0 = (size_t)(bM * 256 + wm * 64 + mt * 16 + g8);
            #pragma unroll
            for (int nt = 0; nt < 8; ++nt) {
                const int col = bN * 128 + wn * 64 + nt * 8 + qid * 2;
                float2 ga = *(const float2*)(C + r0 * LDC + col);
                float2 gb = *(const float2*)(C + (r0 + 8) * LDC + col);
                acc[mt][nt][0] = ga.x; acc[mt][nt][1] = ga.y;
                acc[mt][nt][2] = gb.x; acc[mt][nt][3] = gb.y;
            }
        }
    } else {
        #pragma unroll
        for (int mt = 0; mt < 4; ++mt)
            #pragma unroll
            for (int nt = 0; nt < 8; ++nt)
                #pragma unroll
                for (int j = 0; j < 4; ++j) acc[mt][nt][j] = 0.f;
    }

    cp_wait1();
    __syncthreads();
    ldF(af0, bf0, KO(0), KO(0));

    unsigned curA = 0, curB = 0;
    for (int kt = 0; kt < NKT; ++kt) {
        ldF(af1, bf1, curA + KO(1), curB + KO(1));    // step 1
        mmaF(af0, bf0);                               // step 0
        if (kt + 2 < NKT) stageLoad();                // issued under MMA shadow
        else cp_commit();                             // keep group accounting in order
        ldF(af0, bf0, curA + KO(2), curB + KO(2));    // step 2
        mmaF(af1, bf1);                               // step 1
        ldF(af1, bf1, curA + KO(3), curB + KO(3));    // step 3
        mmaF(af0, bf0);                               // step 2
        mmaF(af1, bf1);                               // step 3 — full backlog queued

        cp_wait1();          // stage kt+1 done (2-iter-old); kt+2 may still fly
        __syncthreads();     // hides under HMMA drain

        curA = (curA == (STAGES - 1) * A_STAGE_B) ? 0u : curA + A_STAGE_B;
        curB = (curB == (STAGES - 1) * B_STAGE_B) ? 0u : curB + B_STAGE_B;
        if (kt + 1 < NKT) ldF(af0, bf0, curA + KO(0), curB + KO(0));  // next tile step 0
    }

    // epilogue (MODE 1: write-only — g already in acc)
    #pragma unroll
    for (int mt = 0; mt < 4; ++mt) {
        int r0 = bM * 256 + wm * 64 + mt * 16 + g8;
        #pragma unroll
        for (int nt = 0; nt < 8; ++nt) {
            int col  = bN * 128 + wn * 64 + nt * 8 + qid * 2;
            int colL = wn * 64 + nt * 8 + qid * 2;
            if (MODE == 0) {
                float b0 = sBias[colL];
                float b1 = sBias[colL + 1];
                float x0 = acc[mt][nt][0] + b0;
                float x1 = acc[mt][nt][1] + b1;
                float x2 = acc[mt][nt][2] + b0;
                float x3 = acc[mt][nt][3] + b1;
                if (g8 == 0) {   // rows%8==0 are t==0: relu + fp16 h0
                    x0 = fmaxf(x0, 0.f); x1 = fmaxf(x1, 0.f);
                    x2 = fmaxf(x2, 0.f); x3 = fmaxf(x3, 0.f);
                    *(__half2*)(Hout + (size_t)r0 * ldH + col)       = __floats2half2_rn(x0, x1);
                    *(__half2*)(Hout + (size_t)(r0 + 8) * ldH + col) = __floats2half2_rn(x2, x3);
                }
                *(float2*)(C + (size_t)r0 * LDC + col)       = make_float2(x0, x1);
                *(float2*)(C + (size_t)(r0 + 8) * LDC + col) = make_float2(x2, x3);
            } else {
                float x0 = fmaxf(acc[mt][nt][0], 0.f);
                float x1 = fmaxf(acc[mt][nt][1], 0.f);
                float x2 = fmaxf(acc[mt][nt][2], 0.f);
                float x3 = fmaxf(acc[mt][nt][3], 0.f);
                *(float2*)(C + (size_t)r0 * LDC + col)       = make_float2(x0, x1);
                *(float2*)(C + (size_t)(r0 + 8) * LDC + col) = make_float2(x2, x3);
                *(__half2*)(Hout + (size_t)r0 * ldH + col)       = __floats2half2_rn(x0, x1);
                *(__half2*)(Hout + (size_t)(r0 + 8) * ldH + col) = __floats2half2_rn(x2, x3);
            }
        }
    }
}

// pack two fp32 sources (widths 512 and 1024) into one fp16 row of 1536.
// One row per block, 192 threads, no integer division.
template<int DST>  // 0 -> g_A16, 1 -> g_W16
__global__ void pack16(const float* __restrict__ s0, const float* __restrict__ s1)
{
    __half* dst = DST ? g_W16 : g_A16;
    const int row = blockIdx.x;
    const int c8  = threadIdx.x * 8;
    const float* p = (c8 < 512) ? (s0 + (size_t)row * 512 + c8)
                                : (s1 + (size_t)row * 1024 + (c8 - 512));
    float4 v0 = ((const float4*)p)[0];
    float4 v1 = ((const float4*)p)[1];
    __half2 h0 = __floats2half2_rn(v0.x, v0.y);
    __half2 h1 = __floats2half2_rn(v0.z, v0.w);
    __half2 h2 = __floats2half2_rn(v1.x, v1.y);
    __half2 h3 = __floats2half2_rn(v1.z, v1.w);
    uint4 o = make_uint4(*(unsigned*)&h0, *(unsigned*)&h1, *(unsigned*)&h2, *(unsigned*)&h3);
    *(uint4*)(dst + (size_t)row * 1536 + c8) = o;
}

__global__ void cvt16(const float* __restrict__ src, int n)   // -> g_Wh16
{
    size_t i = ((size_t)blockIdx.x * 256 + threadIdx.x) * 8;
    if (i >= (size_t)n) return;
    float4 v0 = ((const float4*)(src + i))[0];
    float4 v1 = ((const float4*)(src + i))[1];
    __half2 h0 = __floats2half2_rn(v0.x, v0.y);
    __half2 h1 = __floats2half2_rn(v0.z, v0.w);
    __half2 h2 = __floats2half2_rn(v1.x, v1.y);
    __half2 h3 = __floats2half2_rn(v1.z, v1.w);
    *(uint4*)(g_Wh16 + i) = make_uint4(*(unsigned*)&h0, *(unsigned*)&h1,
                                       *(unsigned*)&h2, *(unsigned*)&h3);
}

// need[h, b] = out[b, 7, h]
__global__ void transpose_k(const float* __restrict__ out, float* __restrict__ need)
{
    __shared__ float tile[32][33];
    int h0 = blockIdx.x * 32;
    int b0 = blockIdx.y * 32;
    int x = threadIdx.x;
    int y = threadIdx.y;
    #pragma unroll
    for (int j = 0; j < 32; j += 8)
        tile[y + j][x] = out[(size_t)(b0 + y + j) * 8192 + 7168 + h0 + x];
    __syncthreads();
    #pragma unroll
    for (int j = 0; j < 32; j += 8)
        need[(size_t)(h0 + y + j) * 8192 + b0 + x] = tile[x][y + j];
}

extern "C" void kernel_launch(void* const* d_in, const int* in_sizes, int n_in,
                              void* d_out, int out_size)
{
    const float* entity   = (const float*)d_in[0];
    const float* relation = (const float*)d_in[1];
    const float* We       = (const float*)d_in[2];
    const float* be       = (const float*)d_in[3];
    const float* Wr       = (const float*)d_in[4];
    const float* br       = (const float*)d_in[5];
    const float* Wh       = (const float*)d_in[6];
    const float* bh       = (const float*)d_in[7];

    float* out  = (float*)d_out;               // [65536, 1024]
    float* need = out + (size_t)65536 * 1024;  // [1024, 8192]

    cudaFuncSetAttribute(gemm16<0>, cudaFuncAttributeMaxDynamicSharedMemorySize, SMEM_SZ);
    cudaFuncSetAttribute(gemm16<1>, cudaFuncAttributeMaxDynamicSharedMemorySize, SMEM_SZ);

    // prepass: fp16 conversions
    pack16<0><<<65536, 192>>>(entity, relation);
    pack16<1><<<1024, 192>>>(We, Wr);
    cvt16<<<(1024 * 1024 / 8 + 255) / 256, 256>>>(Wh, 1024 * 1024);

    // projection: M tiles = 256, N tiles = 8 (bN fastest -> A-block L2 reuse)
    gemm16<0><<<dim3(8, 256), 256, SMEM_SZ>>>(0, be, br, bh, out);

    // recurrence: M tiles = 32, N tiles = 8
    for (int t = 1; t < 8; ++t)
        gemm16<1><<<dim3(8, 32), 256, SMEM_SZ>>>(t, nullptr, nullptr, nullptr,
                                                 out + (size_t)t * 1024);

    transpose_k<<<dim3(32, 256), dim3(32, 8)>>>(out, need);
}

// round 17
// speedup vs baseline: 1.1527x; 1.0063x over previous
#include <cuda_runtime.h>
#include <cuda_fp16.h>
#include <cstdint>

// RNNModel: g = [E|R]@[We|Wr]^T + (be+br+bh)  (proj, relu on t==0 rows)
//           h_t = relu(g_t + h_{t-1}@Wh^T)    (persistent kernel, 7 steps)
//           need = h_7^T
// R16 (best: 1018us) + R17: persistent recurrence — one launch, 128 CTAs,
//     2 tiles/CTA/step, device-wide atomic barrier between timesteps.
//     Per-tile GEMM pipeline identical to R15/R16 (frag double-buffer,
//     ks-stagger, g-preloaded accumulators, write-only epilogue).
// NOTE: tcgen05 unusable in this harness build (ptxas targets compute_103 base).

#define STAGES    3
#define SROWB     144                   // bytes per smem row (64 halfs + pad)
#define A_STAGE_B (256 * SROWB)         // 36864
#define B_STAGE_B (128 * SROWB)         // 18432
#define A_REGION  (STAGES * A_STAGE_B)  // 110592
#define SMEM_SZ   (A_REGION + STAGES * B_STAGE_B + 512)   // 166400

// fp16 scratch (device-global: allocation-free)
__device__ __half g_A16[(size_t)65536 * 1536];   // packed [E|R]
__device__ __half g_W16[1024 * 1536];            // packed [We|Wr]
__device__ __half g_Wh16[1024 * 1024];
__device__ __half g_H16[(size_t)65536 * 1024];   // h_t fp16, same row indexing as out
__device__ unsigned g_barCount;                  // monotonic; replay-safe barrier

__device__ __forceinline__ void mma_f16(float c[4], const unsigned a[4], const unsigned b[2]) {
    asm volatile(
        "mma.sync.aligned.m16n8k16.row.col.f32.f16.f16.f32 "
        "{%0,%1,%2,%3}, {%4,%5,%6,%7}, {%8,%9}, {%0,%1,%2,%3};\n"
        : "+f"(c[0]), "+f"(c[1]), "+f"(c[2]), "+f"(c[3])
        : "r"(a[0]), "r"(a[1]), "r"(a[2]), "r"(a[3]),
          "r"(b[0]), "r"(b[1]));
}
__device__ __forceinline__ void ldsm_x4(unsigned& r0, unsigned& r1, unsigned& r2, unsigned& r3,
                                        unsigned addr) {
    asm volatile("ldmatrix.sync.aligned.m8n8.x4.shared.b16 {%0,%1,%2,%3}, [%4];\n"
                 : "=r"(r0), "=r"(r1), "=r"(r2), "=r"(r3)
                 : "r"(addr));
}
__device__ __forceinline__ void cp16(unsigned dst, const __half* src) {
    asm volatile("cp.async.cg.shared.global [%0], [%1], 16;" :: "r"(dst), "l"(src));
}
__device__ __forceinline__ void cp_commit() {
    asm volatile("cp.async.commit_group;" ::: "memory");
}
__device__ __forceinline__ void cp_wait1() {
    asm volatile("cp.async.wait_group 1;" ::: "memory");
}

// ---------------- projection kernel (unchanged from R16 best) ----------------
__global__ __launch_bounds__(256, 1)
void proj16(const float* __restrict__ be, const float* __restrict__ br,
            const float* __restrict__ bhp, float* C)
{
    constexpr int NKT = 24;
    constexpr int LDA = 1536, LDB = 1536, LDC = 1024;

    extern __shared__ __align__(16) char sm[];
    float* sBias = (float*)(sm + A_REGION + STAGES * B_STAGE_B);
    const unsigned smBase = (unsigned)__cvta_generic_to_shared(sm);

    const int tid = threadIdx.x;
    const int bN  = blockIdx.x;
    const int bM  = blockIdx.y;

    if (tid < 128) {
        int c = bN * 128 + tid;
        sBias[tid] = be[c] + br[c] + bhp[c];
    }

    const int lane = tid & 31;
    const int warp = tid >> 5;
    const int wm = warp & 3;
    const int wn = warp >> 2;
    const int g8  = lane >> 2;
    const int qid = lane & 3;
    const unsigned kph = wn ? 64u : 0u;
    auto KO = [&](int s) -> unsigned { return (kph + (unsigned)s * 32u) & 96u; };

    const int srow = tid >> 3;
    const int sch  = tid & 7;
    const __half* aG = g_A16 + (size_t)(bM * 256 + srow) * LDA + sch * 8;
    const __half* bG = g_W16 + (size_t)(bN * 128 + srow) * LDB + sch * 8;
    const unsigned dA0 = smBase + srow * SROWB + sch * 16;
    const unsigned dB0 = smBase + A_REGION + srow * SROWB + sch * 16;
    int stIdx = 0;

    auto stageLoad = [&]() {
        const unsigned sA = dA0 + stIdx * A_STAGE_B;
        const unsigned sB = dB0 + stIdx * B_STAGE_B;
        #pragma unroll
        for (int i = 0; i < 8; ++i)
            cp16(sA + i * (32 * SROWB), aG + (size_t)i * 32 * LDA);
        #pragma unroll
        for (int i = 0; i < 4; ++i)
            cp16(sB + i * (32 * SROWB), bG + (size_t)i * 32 * LDB);
        cp_commit();
        aG += 64; bG += 64;
        stIdx = (stIdx == STAGES - 1) ? 0 : stIdx + 1;
    };

    const int rA = wm * 64 + (lane & 7) + ((lane >> 3) & 1) * 8;
    const int kselA = (lane >> 4) & 1;
    const unsigned aAddr0 = smBase + (unsigned)(rA * SROWB + kselA * 16);
    const int rB = wn * 64 + (lane & 7) + ((lane >> 4) & 1) * 8;
    const int kselB = (lane >> 3) & 1;
    const unsigned bAddr0 = smBase + (unsigned)(A_REGION + rB * SROWB + kselB * 16);

    unsigned af0[4][4], af1[4][4], bf0[8][2], bf1[8][2];
    auto ldF = [&](unsigned (&af)[4][4], unsigned (&bf)[8][2], unsigned offA, unsigned offB) {
        #pragma unroll
        for (int mt = 0; mt < 4; ++mt)
            ldsm_x4(af[mt][0], af[mt][1], af[mt][2], af[mt][3],
                    aAddr0 + offA + mt * (16 * SROWB));
        #pragma unroll
        for (int p = 0; p < 4; ++p)
            ldsm_x4(bf[2 * p][0], bf[2 * p][1], bf[2 * p + 1][0], bf[2 * p + 1][1],
                    bAddr0 + offB + p * (16 * SROWB));
    };

    float acc[4][8][4];
    #pragma unroll
    for (int mt = 0; mt < 4; ++mt)
        #pragma unroll
        for (int nt = 0; nt < 8; ++nt)
            #pragma unroll
            for (int j = 0; j < 4; ++j) acc[mt][nt][j] = 0.f;

    auto mmaF = [&](unsigned (&af)[4][4], unsigned (&bf)[8][2]) {
        #pragma unroll
        for (int mt = 0; mt < 4; ++mt)
            #pragma unroll
            for (int nt = 0; nt < 8; ++nt)
                mma_f16(acc[mt][nt], af[mt], bf[nt]);
    };

    stageLoad(); stageLoad();
    cp_wait1();
    __syncthreads();
    ldF(af0, bf0, KO(0), KO(0));

    unsigned curA = 0, curB = 0;
    for (int kt = 0; kt < NKT; ++kt) {
        ldF(af1, bf1, curA + KO(1), curB + KO(1));
        mmaF(af0, bf0);
        if (kt + 2 < NKT) stageLoad();
        else cp_commit();
        ldF(af0, bf0, curA + KO(2), curB + KO(2));
        mmaF(af1, bf1);
        ldF(af1, bf1, curA + KO(3), curB + KO(3));
        mmaF(af0, bf0);
        mmaF(af1, bf1);
        cp_wait1();
        __syncthreads();
        curA = (curA == (STAGES - 1) * A_STAGE_B) ? 0u : curA + A_STAGE_B;
        curB = (curB == (STAGES - 1) * B_STAGE_B) ? 0u : curB + B_STAGE_B;
        if (kt + 1 < NKT) ldF(af0, bf0, curA + KO(0), curB + KO(0));
    }

    #pragma unroll
    for (int mt = 0; mt < 4; ++mt) {
        int r0 = bM * 256 + wm * 64 + mt * 16 + g8;
        #pragma unroll
        for (int nt = 0; nt < 8; ++nt) {
            int col  = bN * 128 + wn * 64 + nt * 8 + qid * 2;
            int colL = wn * 64 + nt * 8 + qid * 2;
            float b0 = sBias[colL];
            float b1 = sBias[colL + 1];
            float x0 = acc[mt][nt][0] + b0;
            float x1 = acc[mt][nt][1] + b1;
            float x2 = acc[mt][nt][2] + b0;
            float x3 = acc[mt][nt][3] + b1;
            if (g8 == 0) {   // rows%8==0 are t==0: relu + fp16 h0
                x0 = fmaxf(x0, 0.f); x1 = fmaxf(x1, 0.f);
                x2 = fmaxf(x2, 0.f); x3 = fmaxf(x3, 0.f);
                *(__half2*)(g_H16 + (size_t)r0 * 1024 + col)       = __floats2half2_rn(x0, x1);
                *(__half2*)(g_H16 + (size_t)(r0 + 8) * 1024 + col) = __floats2half2_rn(x2, x3);
            }
            *(float2*)(C + (size_t)r0 * LDC + col)       = make_float2(x0, x1);
            *(float2*)(C + (size_t)(r0 + 8) * LDC + col) = make_float2(x2, x3);
        }
    }
}

// ---------------- persistent recurrence kernel ----------------
__global__ __launch_bounds__(256, 1)
void rec16(float* out)
{
    constexpr int NKT = 16;
    constexpr int LDA = 8192, LDB = 1024, LDC = 8192, LDH = 8192;

    extern __shared__ __align__(16) char sm[];
    const unsigned smBase = (unsigned)__cvta_generic_to_shared(sm);

    const int tid = threadIdx.x;
    const int cta = blockIdx.x;          // 0..127

    const int lane = tid & 31;
    const int warp = tid >> 5;
    const int wm = warp & 3;
    const int wn = warp >> 2;
    const int g8  = lane >> 2;
    const int qid = lane & 3;
    const unsigned kph = wn ? 64u : 0u;
    auto KO = [&](int s) -> unsigned { return (kph + (unsigned)s * 32u) & 96u; };

    const int srow = tid >> 3;
    const int sch  = tid & 7;
    const unsigned dA0 = smBase + srow * SROWB + sch * 16;
    const unsigned dB0 = smBase + A_REGION + srow * SROWB + sch * 16;

    const int rA = wm * 64 + (lane & 7) + ((lane >> 3) & 1) * 8;
    const int kselA = (lane >> 4) & 1;
    const unsigned aAddr0 = smBase + (unsigned)(rA * SROWB + kselA * 16);
    const int rB = wn * 64 + (lane & 7) + ((lane >> 4) & 1) * 8;
    const int kselB = (lane >> 3) & 1;
    const unsigned bAddr0 = smBase + (unsigned)(A_REGION + rB * SROWB + kselB * 16);

    unsigned af0[4][4], af1[4][4], bf0[8][2], bf1[8][2];
    auto ldF = [&](unsigned (&af)[4][4], unsigned (&bf)[8][2], unsigned offA, unsigned offB) {
        #pragma unroll
        for (int mt = 0; mt < 4; ++mt)
            ldsm_x4(af[mt][0], af[mt][1], af[mt][2], af[mt][3],
                    aAddr0 + offA + mt * (16 * SROWB));
        #pragma unroll
        for (int p = 0; p < 4; ++p)
            ldsm_x4(bf[2 * p][0], bf[2 * p][1], bf[2 * p + 1][0], bf[2 * p + 1][1],
                    bAddr0 + offB + p * (16 * SROWB));
    };

    float acc[4][8][4];
    auto mmaF = [&](unsigned (&af)[4][4], unsigned (&bf)[8][2]) {
        #pragma unroll
        for (int mt = 0; mt < 4; ++mt)
            #pragma unroll
            for (int nt = 0; nt < 8; ++nt)
                mma_f16(acc[mt][nt], af[mt], bf[nt]);
    };

    for (int t = 1; t < 8; ++t) {
        const __half* Abase = g_H16 + (size_t)(t - 1) * 1024;
        __half* Hout = g_H16 + (size_t)t * 1024;
        float* C = out + (size_t)t * 1024;

        #pragma unroll 1
        for (int half = 0; half < 2; ++half) {
            const int id = cta + half * 128;
            const int bN = id & 7;
            const int bM = id >> 3;

            const __half* aG = Abase + (size_t)(bM * 256 + srow) * LDA + sch * 8;
            const __half* bG = g_Wh16 + (size_t)(bN * 128 + srow) * LDB + sch * 8;
            int stIdx = 0;

            auto stageLoad = [&]() {
                const unsigned sA = dA0 + stIdx * A_STAGE_B;
                const unsigned sB = dB0 + stIdx * B_STAGE_B;
                #pragma unroll
                for (int i = 0; i < 8; ++i)
                    cp16(sA + i * (32 * SROWB), aG + (size_t)i * 32 * LDA);
                #pragma unroll
                for (int i = 0; i < 4; ++i)
                    cp16(sB + i * (32 * SROWB), bG + (size_t)i * 32 * LDB);
                cp_commit();
                aG += 64; bG += 64;
                stIdx = (stIdx == STAGES - 1) ? 0 : stIdx + 1;
            };

            // prologue: async loads first, then g-preload (latency overlapped)
            stageLoad(); stageLoad();
            #pragma unroll
            for (int mt = 0; mt < 4; ++mt) {
                const size_t r0 = (size_t)(bM * 256 + wm * 64 + mt * 16 + g8);
                #pragma unroll
                for (int nt = 0; nt < 8; ++nt) {
                    const int col = bN * 128 + wn * 64 + nt * 8 + qid * 2;
                    float2 ga = *(const float2*)(C + r0 * LDC + col);
                    float2 gb = *(const float2*)(C + (r0 + 8) * LDC + col);
                    acc[mt][nt][0] = ga.x; acc[mt][nt][1] = ga.y;
                    acc[mt][nt][2] = gb.x; acc[mt][nt][3] = gb.y;
                }
            }
            cp_wait1();
            __syncthreads();
            ldF(af0, bf0, KO(0), KO(0));

            unsigned curA = 0, curB = 0;
            for (int kt = 0; kt < NKT; ++kt) {
                ldF(af1, bf1, curA + KO(1), curB + KO(1));
                mmaF(af0, bf0);
                if (kt + 2 < NKT) stageLoad();
                else cp_commit();
                ldF(af0, bf0, curA + KO(2), curB + KO(2));
                mmaF(af1, bf1);
                ldF(af1, bf1, curA + KO(3), curB + KO(3));
                mmaF(af0, bf0);
                mmaF(af1, bf1);
                cp_wait1();
                __syncthreads();
                curA = (curA == (STAGES - 1) * A_STAGE_B) ? 0u : curA + A_STAGE_B;
                curB = (curB == (STAGES - 1) * B_STAGE_B) ? 0u : curB + B_STAGE_B;
                if (kt + 1 < NKT) ldF(af0, bf0, curA + KO(0), curB + KO(0));
            }

            // epilogue: write-only (g already in acc)
            #pragma unroll
            for (int mt = 0; mt < 4; ++mt) {
                int r0 = bM * 256 + wm * 64 + mt * 16 + g8;
                #pragma unroll
                for (int nt = 0; nt < 8; ++nt) {
                    int col = bN * 128 + wn * 64 + nt * 8 + qid * 2;
                    float x0 = fmaxf(acc[mt][nt][0], 0.f);
                    float x1 = fmaxf(acc[mt][nt][1], 0.f);
                    float x2 = fmaxf(acc[mt][nt][2], 0.f);
                    float x3 = fmaxf(acc[mt][nt][3], 0.f);
                    *(float2*)(C + (size_t)r0 * LDC + col)       = make_float2(x0, x1);
                    *(float2*)(C + (size_t)(r0 + 8) * LDC + col) = make_float2(x2, x3);
                    *(__half2*)(Hout + (size_t)r0 * LDH + col)       = __floats2half2_rn(x0, x1);
                    *(__half2*)(Hout + (size_t)(r0 + 8) * LDH + col) = __floats2half2_rn(x2, x3);
                }
            }
            __syncthreads();   // smem safe for next tile's prologue
        }

        // device-wide barrier (replay-safe: monotonic counter, round up to 128)
        __threadfence();
        if (tid == 0) {
            unsigned arrival = atomicAdd(&g_barCount, 1u) + 1u;
            unsigned target  = ((arrival + 127u) >> 7) << 7;   // ceil to multiple of 128
            while (*(volatile unsigned*)&g_barCount < target) { }
        }
        __syncthreads();
        __threadfence();
    }
}

// pack two fp32 sources (widths 512 and 1024) into one fp16 row of 1536.
template<int DST>  // 0 -> g_A16, 1 -> g_W16
__global__ void pack16(const float* __restrict__ s0, const float* __restrict__ s1)
{
    __half* dst = DST ? g_W16 : g_A16;
    const int row = blockIdx.x;
    const int c8  = threadIdx.x * 8;
    const float* p = (c8 < 512) ? (s0 + (size_t)row * 512 + c8)
                                : (s1 + (size_t)row * 1024 + (c8 - 512));
    float4 v0 = ((const float4*)p)[0];
    float4 v1 = ((const float4*)p)[1];
    __half2 h0 = __floats2half2_rn(v0.x, v0.y);
    __half2 h1 = __floats2half2_rn(v0.z, v0.w);
    __half2 h2 = __floats2half2_rn(v1.x, v1.y);
    __half2 h3 = __floats2half2_rn(v1.z, v1.w);
    uint4 o = make_uint4(*(unsigned*)&h0, *(unsigned*)&h1, *(unsigned*)&h2, *(unsigned*)&h3);
    *(uint4*)(dst + (size_t)row * 1536 + c8) = o;
}

__global__ void cvt16(const float* __restrict__ src, int n)   // -> g_Wh16
{
    size_t i = ((size_t)blockIdx.x * 256 + threadIdx.x) * 8;
    if (i >= (size_t)n) return;
    float4 v0 = ((const float4*)(src + i))[0];
    float4 v1 = ((const float4*)(src + i))[1];
    __half2 h0 = __floats2half2_rn(v0.x, v0.y);
    __half2 h1 = __floats2half2_rn(v0.z, v0.w);
    __half2 h2 = __floats2half2_rn(v1.x, v1.y);
    __half2 h3 = __floats2half2_rn(v1.z, v1.w);
    *(uint4*)(g_Wh16 + i) = make_uint4(*(unsigned*)&h0, *(unsigned*)&h1,
                                       *(unsigned*)&h2, *(unsigned*)&h3);
}

// need[h, b] = out[b, 7, h]
__global__ void transpose_k(const float* __restrict__ out, float* __restrict__ need)
{
    __shared__ float tile[32][33];
    int h0 = blockIdx.x * 32;
    int b0 = blockIdx.y * 32;
    int x = threadIdx.x;
    int y = threadIdx.y;
    #pragma unroll
    for (int j = 0; j < 32; j += 8)
        tile[y + j][x] = out[(size_t)(b0 + y + j) * 8192 + 7168 + h0 + x];
    __syncthreads();
    #pragma unroll
    for (int j = 0; j < 32; j += 8)
        need[(size_t)(h0 + y + j) * 8192 + b0 + x] = tile[x][y + j];
}

extern "C" void kernel_launch(void* const* d_in, const int* in_sizes, int n_in,
                              void* d_out, int out_size)
{
    const float* entity   = (const float*)d_in[0];
    const float* relation = (const float*)d_in[1];
    const float* We       = (const float*)d_in[2];
    const float* be       = (const float*)d_in[3];
    const float* Wr       = (const float*)d_in[4];
    const float* br       = (const float*)d_in[5];
    const float* Wh       = (const float*)d_in[6];
    const float* bh       = (const float*)d_in[7];

    float* out  = (float*)d_out;               // [65536, 1024]
    float* need = out + (size_t)65536 * 1024;  // [1024, 8192]

    cudaFuncSetAttribute(proj16, cudaFuncAttributeMaxDynamicSharedMemorySize, SMEM_SZ);
    cudaFuncSetAttribute(rec16,  cudaFuncAttributeMaxDynamicSharedMemorySize, SMEM_SZ);

    // prepass: fp16 conversions
    pack16<0><<<65536, 192>>>(entity, relation);
    pack16<1><<<1024, 192>>>(We, Wr);
    cvt16<<<(1024 * 1024 / 8 + 255) / 256, 256>>>(Wh, 1024 * 1024);

    // projection: M tiles = 256, N tiles = 8 (bN fastest -> A-block L2 reuse)
    proj16<<<dim3(8, 256), 256, SMEM_SZ>>>(be, br, bh, out);

    // recurrence: one persistent launch, 128 CTAs, internal barrier per step
    rec16<<<128, 256, SMEM_SZ>>>(out);

    transpose_k<<<dim3(32, 256), dim3(32, 8)>>>(out, need);
}